// round 4
// baseline (speedup 1.0000x reference)
#include <cuda_runtime.h>

// y[i,o,n] = sum_j sum_k x[j,(o-1)%28, n+k-1]*W[i,j,0,k]
//                      + x[j,(o-2)%28, n+k-1]*W[i,j,1,k]
// x: (64,28,28) f32, W: (128,64,2,3) f32, y: (128,28,28) f32, zero-pad over n.
//
// Block: 32 channels (i) x 4 rows (o) x 28 cols (n), 4 j-channels.
// Grid (4, 7, 16) = 448 blocks, 256 threads (8 warps) -> ~24 warps/SM.
// Thread tile: 4 i x 4 n (warp w owns i_local {4w..4w+3}; lane -> (ol, ng)).
// j-split partials combined via atomicAdd after cudaMemsetAsync(out, 0).

#define JT 4    // j per block
#define IC 32   // channels per block

__global__ __launch_bounds__(256, 4)
void conv_shift_kernel(const float* __restrict__ x,
                       const float* __restrict__ W,
                       float* __restrict__ out) {
    // x rows staged padded: padded index p = n+1, p=0..29 (stride 34 de-phases banks)
    __shared__ __align__(16) float xs[JT][6][34];
    // weights: [j][i_local][ l*4 + k ], float4-loadable; slots 3,7 are pad
    __shared__ __align__(16) float ws[JT][IC][8];

    const int tid = threadIdx.x;
    const int ib = blockIdx.x * IC;  // channel base
    const int ob = blockIdx.y * 4;   // o base (0..24)
    const int jb = blockIdx.z * JT;  // j base

    // Zero the n-pad columns
    if (tid < JT * 6) {
        int jl = tid / 6, rl = tid - jl * 6;
        xs[jl][rl][0]  = 0.0f;
        xs[jl][rl][29] = 0.0f;
    }
    // Stage x rows: row_local rl = global row (ob - 2 + rl) mod 28
    for (int idx = tid; idx < JT * 6 * 28; idx += 256) {
        int jl  = idx / 168;
        int rem = idx - jl * 168;
        int rl  = rem / 28;
        int n   = rem - rl * 28;
        int row = ob - 2 + rl;
        row = (row + 28) % 28;
        xs[jl][rl][n + 1] = x[(jb + jl) * 784 + row * 28 + n];
    }
    // Stage weights
    for (int idx = tid; idx < JT * IC * 6; idx += 256) {
        int jl  = idx / (IC * 6);
        int rem = idx - jl * (IC * 6);
        int il  = rem / 6;
        int q   = rem - il * 6;
        int l   = q / 3;
        int k   = q - l * 3;
        ws[jl][il][l * 4 + k] = W[(ib + il) * 384 + (jb + jl) * 6 + l * 3 + k];
    }
    __syncthreads();

    const int warp = tid >> 5;
    const int lane = tid & 31;
    const int ol = lane / 7;   // 0..3 (lanes 28..31 compute redundantly, masked at store)
    const int ng = lane % 7;   // 0..6 -> n0 = 4*ng
    const int il0 = warp * 4;
    const int n0 = 4 * ng;

    float acc[4][4];
    #pragma unroll
    for (int c = 0; c < 4; c++)
        #pragma unroll
        for (int n = 0; n < 4; n++) acc[c][n] = 0.0f;

    #pragma unroll
    for (int jl = 0; jl < JT; jl++) {
        // x taps for rows (o-1) and (o-2): padded indices n0 .. n0+5
        const float* p1 = &xs[jl][ol + 1][n0];
        const float* p2 = &xs[jl][ol][n0];

        float v1[6], v2[6];
        #pragma unroll
        for (int t = 0; t < 3; t++) {
            float2 u1 = *reinterpret_cast<const float2*>(p1 + 2 * t);
            float2 u2 = *reinterpret_cast<const float2*>(p2 + 2 * t);
            v1[2 * t] = u1.x; v1[2 * t + 1] = u1.y;
            v2[2 * t] = u2.x; v2[2 * t + 1] = u2.y;
        }

        #pragma unroll
        for (int c = 0; c < 4; c++) {
            const float4 a0 = *reinterpret_cast<const float4*>(&ws[jl][il0 + c][0]); // l=0 (row o-1)
            const float4 a1 = *reinterpret_cast<const float4*>(&ws[jl][il0 + c][4]); // l=1 (row o-2)
            const float wa0[3] = {a0.x, a0.y, a0.z};
            const float wa1[3] = {a1.x, a1.y, a1.z};
            #pragma unroll
            for (int n = 0; n < 4; n++) {
                #pragma unroll
                for (int k = 0; k < 3; k++) {
                    acc[c][n] = fmaf(v1[n + k], wa0[k], acc[c][n]);
                    acc[c][n] = fmaf(v2[n + k], wa1[k], acc[c][n]);
                }
            }
        }
    }

    if (lane < 28) {
        const int o = ob + ol;
        #pragma unroll
        for (int c = 0; c < 4; c++) {
            float* d = out + (ib + il0 + c) * 784 + o * 28 + n0;
            #pragma unroll
            for (int n = 0; n < 4; n++) {
                atomicAdd(&d[n], acc[c][n]);
            }
        }
    }
}

extern "C" void kernel_launch(void* const* d_in, const int* in_sizes, int n_in,
                              void* d_out, int out_size) {
    const float* x = (const float*)d_in[0];  // (1,64,28,28)  = 50176 f32
    const float* W = (const float*)d_in[1];  // (128,64,2,3) = 147456 f32
    float* out = (float*)d_out;              // (1,128,28,28) = 100352 f32

    cudaMemsetAsync(out, 0, (size_t)out_size * sizeof(float));

    dim3 grid(4, 7, 16);  // (i-groups of 32, o-groups of 4, j-groups of 4)
    conv_shift_kernel<<<grid, 256>>>(x, W, out);
}

// round 5
// speedup vs baseline: 1.0025x; 1.0025x over previous
#include <cuda_runtime.h>

// y[i,o,n] = sum_j sum_k x[j,(o-1)%28, n+k-1]*W[i,j,0,k]
//                      + x[j,(o-2)%28, n+k-1]*W[i,j,1,k]
// x: (64,28,28) f32, W: (128,64,2,3) f32, y: (128,28,28) f32, zero-pad over n.
//
// Stage 1: grid (4,7,16), 256 thr. Each j-group of 4 writes partials (STG.128,
//          no atomics) to a __device__ scratch slab: scratch[p][i*784+o*28+n].
// Stage 2: 98 blocks x 256 thr; each thread sums 16 float4 partials -> out.

#define JT 4    // j per block (stage 1)
#define IC 32   // channels per block
#define NSPLIT 16

__device__ __align__(16) float g_scratch[NSPLIT * 128 * 28 * 28];

__global__ __launch_bounds__(256, 4)
void conv_partial_kernel(const float* __restrict__ x,
                         const float* __restrict__ W) {
    // x rows staged padded: padded index p = n+1, p=0..29 (stride 34 de-phases banks)
    __shared__ __align__(16) float xs[JT][6][34];
    // weights: [j][i_local][ l*4 + k ], float4-loadable; slots 3,7 are pad
    __shared__ __align__(16) float ws[JT][IC][8];

    const int tid = threadIdx.x;
    const int ib = blockIdx.x * IC;  // channel base
    const int ob = blockIdx.y * 4;   // o base (0..24)
    const int jb = blockIdx.z * JT;  // j base

    // Zero the n-pad columns
    if (tid < JT * 6) {
        int jl = tid / 6, rl = tid - jl * 6;
        xs[jl][rl][0]  = 0.0f;
        xs[jl][rl][29] = 0.0f;
    }
    // Stage x rows: row_local rl = global row (ob - 2 + rl) mod 28
    for (int idx = tid; idx < JT * 6 * 28; idx += 256) {
        int jl  = idx / 168;
        int rem = idx - jl * 168;
        int rl  = rem / 28;
        int n   = rem - rl * 28;
        int row = ob - 2 + rl;
        row = (row + 28) % 28;
        xs[jl][rl][n + 1] = x[(jb + jl) * 784 + row * 28 + n];
    }
    // Stage weights
    for (int idx = tid; idx < JT * IC * 6; idx += 256) {
        int jl  = idx / (IC * 6);
        int rem = idx - jl * (IC * 6);
        int il  = rem / 6;
        int q   = rem - il * 6;
        int l   = q / 3;
        int k   = q - l * 3;
        ws[jl][il][l * 4 + k] = W[(ib + il) * 384 + (jb + jl) * 6 + l * 3 + k];
    }
    __syncthreads();

    const int warp = tid >> 5;
    const int lane = tid & 31;
    const int ol = lane / 7;   // 0..3 (lanes 28..31 compute redundantly, masked at store)
    const int ng = lane % 7;   // 0..6 -> n0 = 4*ng
    const int il0 = warp * 4;
    const int n0 = 4 * ng;

    float acc[4][4];
    #pragma unroll
    for (int c = 0; c < 4; c++)
        #pragma unroll
        for (int n = 0; n < 4; n++) acc[c][n] = 0.0f;

    #pragma unroll
    for (int jl = 0; jl < JT; jl++) {
        // x taps for rows (o-1) and (o-2): padded indices n0 .. n0+5
        const float* p1 = &xs[jl][ol + 1][n0];
        const float* p2 = &xs[jl][ol][n0];

        float v1[6], v2[6];
        #pragma unroll
        for (int t = 0; t < 3; t++) {
            float2 u1 = *reinterpret_cast<const float2*>(p1 + 2 * t);
            float2 u2 = *reinterpret_cast<const float2*>(p2 + 2 * t);
            v1[2 * t] = u1.x; v1[2 * t + 1] = u1.y;
            v2[2 * t] = u2.x; v2[2 * t + 1] = u2.y;
        }

        #pragma unroll
        for (int c = 0; c < 4; c++) {
            const float4 a0 = *reinterpret_cast<const float4*>(&ws[jl][il0 + c][0]); // l=0 (row o-1)
            const float4 a1 = *reinterpret_cast<const float4*>(&ws[jl][il0 + c][4]); // l=1 (row o-2)
            const float wa0[3] = {a0.x, a0.y, a0.z};
            const float wa1[3] = {a1.x, a1.y, a1.z};
            #pragma unroll
            for (int n = 0; n < 4; n++) {
                #pragma unroll
                for (int k = 0; k < 3; k++) {
                    acc[c][n] = fmaf(v1[n + k], wa0[k], acc[c][n]);
                    acc[c][n] = fmaf(v2[n + k], wa1[k], acc[c][n]);
                }
            }
        }
    }

    if (lane < 28) {
        const int o = ob + ol;
        float* base = g_scratch + blockIdx.z * (128 * 784);
        #pragma unroll
        for (int c = 0; c < 4; c++) {
            float4 v;
            v.x = acc[c][0]; v.y = acc[c][1]; v.z = acc[c][2]; v.w = acc[c][3];
            *reinterpret_cast<float4*>(base + (ib + il0 + c) * 784 + o * 28 + n0) = v;
        }
    }
}

__global__ __launch_bounds__(256, 8)
void reduce_kernel(float* __restrict__ out) {
    // 128*28*28 = 100352 floats = 25088 float4 outputs; 98 blocks x 256 threads.
    const int idx4 = blockIdx.x * 256 + threadIdx.x;  // 0..25087
    const float4* s = reinterpret_cast<const float4*>(g_scratch);

    float4 v[NSPLIT];
    #pragma unroll
    for (int p = 0; p < NSPLIT; p++)
        v[p] = s[p * 25088 + idx4];

    float4 r;
    r.x = r.y = r.z = r.w = 0.0f;
    #pragma unroll
    for (int p = 0; p < NSPLIT; p++) {
        r.x += v[p].x; r.y += v[p].y; r.z += v[p].z; r.w += v[p].w;
    }
    reinterpret_cast<float4*>(out)[idx4] = r;
}

extern "C" void kernel_launch(void* const* d_in, const int* in_sizes, int n_in,
                              void* d_out, int out_size) {
    const float* x = (const float*)d_in[0];  // (1,64,28,28)  = 50176 f32
    const float* W = (const float*)d_in[1];  // (128,64,2,3) = 147456 f32
    float* out = (float*)d_out;              // (1,128,28,28) = 100352 f32

    dim3 grid(4, 7, NSPLIT);  // (i-groups of 32, o-groups of 4, j-groups of 4)
    conv_partial_kernel<<<grid, 256>>>(x, W);
    reduce_kernel<<<98, 256>>>(out);
}